// round 6
// baseline (speedup 1.0000x reference)
#include <cuda_runtime.h>
#include <cstdint>

// Problem constants (fixed by the reference: B=4, T=2048, S=4, D=1024)
#define BT      8192        // B*T
#define SDIM    4
#define DDIM    1024
#define DVEC    256         // D/4 float4 per row
#define SINKHORN_ITERS 20
#define EPS_SK  1e-8f

// Device-side scratch (allocation-free rule: use __device__ globals).
// All of these are restored to their initial state at the end of every
// kernel run (flag/count reset by the last block), so graph replays are
// deterministic.
__device__ float  d_M[16];                 // M[sp*4+s] = (sp==s) + a_res*P[sp][s]
__device__ float  d_g[4];                  // alpha_pos * H_pos[s]
__device__ float4 d_biasC[SDIM * DVEC];    // bias_res + bias_pos, [s][dvec]
__device__ int      d_flag  = 0;           // set by block 0 when d_M/d_g/d_biasC ready
__device__ unsigned d_count = 0;           // completion ticket for reset

__device__ __forceinline__ float rcp_approx(float x) {
    float r;
    asm("rcp.approx.f32 %0, %1;" : "=f"(r) : "f"(x));
    return r;
}

// ---------------------------------------------------------------------------
// Single kernel. Block 0 computes the 4x4 Sinkhorn (warp 0, lanes 0..15,
// shfl-parallel) and the bias fold (warps 1..7) exactly ONCE, then
// release-publishes via d_flag. All other blocks front-batch their DRAM
// loads and spin (thread 0 only, acquire + nanosleep) until published.
// Waves >= 2 see the flag already set: zero overhead.
//   out[bt,s,dv] = sum_sp M[sp][s]*x[bt,sp,dv] + g[s]*lo[bt,dv] + biasC[s,dv]
// ---------------------------------------------------------------------------
__global__ __launch_bounds__(256)
void mhc_residual_kernel(const float4* __restrict__ x,
                         const float4* __restrict__ lo,
                         const float*  __restrict__ H_res,
                         const float*  __restrict__ H_pos,
                         const float*  __restrict__ alpha_res,
                         const float*  __restrict__ alpha_pos,
                         const float4* __restrict__ br,
                         const float4* __restrict__ bp,
                         float4* __restrict__ out)
{
    const unsigned dvec = threadIdx.x;          // 0..255
    const unsigned bt   = blockIdx.x;           // 0..8191

    // Front-batch the DRAM-bound loads (in flight during the gate below)
    const float4* xr = x + (size_t)bt * (SDIM * DVEC) + dvec;
    float4 x0 = __ldg(xr + 0 * DVEC);
    float4 x1 = __ldg(xr + 1 * DVEC);
    float4 x2 = __ldg(xr + 2 * DVEC);
    float4 x3 = __ldg(xr + 3 * DVEC);
    float4 l  = __ldg(lo + (size_t)bt * DVEC + dvec);

    if (bt == 0) {
        // ---- one-time prep, parallel inside block 0 ----
        if (threadIdx.x < 32) {
            if (threadIdx.x < 16) {
                // Warp-parallel Sinkhorn: lane = r*4 + c holds P[r][c]
                const unsigned lane = threadIdx.x;
                float h = __ldg(H_res + lane);
                float m = fmaxf(h, __shfl_xor_sync(0xffffu, h, 1));
                m = fmaxf(m, __shfl_xor_sync(0xffffu, m, 2));
                float v = __expf(h - m);
                #pragma unroll 1
                for (int it = 0; it < SINKHORN_ITERS; it++) {
                    float s = v + __shfl_xor_sync(0xffffu, v, 1);   // row sum (over c)
                    s += __shfl_xor_sync(0xffffu, s, 2);
                    v *= rcp_approx(s + EPS_SK);
                    float t = v + __shfl_xor_sync(0xffffu, v, 4);   // col sum (over r)
                    t += __shfl_xor_sync(0xffffu, t, 8);
                    v *= rcp_approx(t + EPS_SK);
                }
                float ar = __ldg(alpha_res);
                float diag = ((lane >> 2) == (lane & 3)) ? 1.0f : 0.0f;
                d_M[lane] = diag + ar * v;
                if (lane < 4)
                    d_g[lane] = __ldg(alpha_pos) * __ldg(H_pos + lane);
            }
        } else {
            // Warps 1..7 (224 threads): bias fold, 1024 float4
            for (unsigned j = threadIdx.x - 32; j < SDIM * DVEC; j += 224) {
                float4 a = __ldg(br + j);
                float4 c = __ldg(bp + j);
                float4 b;
                b.x = a.x + c.x; b.y = a.y + c.y; b.z = a.z + c.z; b.w = a.w + c.w;
                d_biasC[j] = b;
            }
        }
        __syncthreads();
        if (threadIdx.x == 0) {
            __threadfence();                               // release d_M/d_g/d_biasC
            asm volatile("st.global.release.gpu.b32 [%0], %1;"
                         :: "l"(&d_flag), "r"(1) : "memory");
        }
    } else {
        if (threadIdx.x == 0) {
            int f;
            asm volatile("ld.global.acquire.gpu.b32 %0, [%1];"
                         : "=r"(f) : "l"(&d_flag) : "memory");
            while (!f) {
                __nanosleep(64);
                asm volatile("ld.global.acquire.gpu.b32 %0, [%1];"
                             : "=r"(f) : "l"(&d_flag) : "memory");
            }
        }
    }
    __syncthreads();   // CTA barrier: publishes block-0 data to all threads

    __shared__ float sM[16];
    __shared__ float sg[4];
    if (threadIdx.x < 16) sM[threadIdx.x] = d_M[threadIdx.x];
    if (threadIdx.x < 4)  sg[threadIdx.x] = d_g[threadIdx.x];
    __syncthreads();

    const float4* bC = (const float4*)d_biasC + dvec;
    float4* outr = out + (size_t)bt * (SDIM * DVEC) + dvec;

#pragma unroll
    for (int s = 0; s < 4; s++) {
        float m0 = sM[0 * 4 + s];
        float m1 = sM[1 * 4 + s];
        float m2 = sM[2 * 4 + s];
        float m3 = sM[3 * 4 + s];
        float g  = sg[s];
        float4 b = __ldg(bC + s * DVEC);       // L2-resident broadcast
        float4 o;
        o.x = fmaf(m0, x0.x, fmaf(m1, x1.x, fmaf(m2, x2.x, fmaf(m3, x3.x, fmaf(g, l.x, b.x)))));
        o.y = fmaf(m0, x0.y, fmaf(m1, x1.y, fmaf(m2, x2.y, fmaf(m3, x3.y, fmaf(g, l.y, b.y)))));
        o.z = fmaf(m0, x0.z, fmaf(m1, x1.z, fmaf(m2, x2.z, fmaf(m3, x3.z, fmaf(g, l.z, b.z)))));
        o.w = fmaf(m0, x0.w, fmaf(m1, x1.w, fmaf(m2, x2.w, fmaf(m3, x3.w, fmaf(g, l.w, b.w)))));
        outr[s * DVEC] = o;
    }

    // ---- replay-safe reset: last block to finish restores flag/count ----
    if (threadIdx.x == 0) {
        __threadfence();
        unsigned c = atomicAdd(&d_count, 1u);
        if (c == (unsigned)gridDim.x - 1u) {
            d_count = 0u;
            asm volatile("st.global.release.gpu.b32 [%0], %1;"
                         :: "l"(&d_flag), "r"(0) : "memory");
        }
    }
}

// ---------------------------------------------------------------------------
// Launch. Inputs per metadata order:
//   0: x (B,T,S,D) f32   1: layer_output (B,T,D) f32   2: H_res (S,S) f32
//   3: H_pos (S,1) f32   4: alpha_res f32 scalar        5: alpha_pos f32 scalar
//   6: bias_res (S,D)    7: bias_pos (S,D)
// ---------------------------------------------------------------------------
extern "C" void kernel_launch(void* const* d_in, const int* in_sizes, int n_in,
                              void* d_out, int out_size)
{
    const float* x         = (const float*)d_in[0];
    const float* lo        = (const float*)d_in[1];
    const float* H_res     = (const float*)d_in[2];
    const float* H_pos     = (const float*)d_in[3];
    const float* alpha_res = (const float*)d_in[4];
    const float* alpha_pos = (const float*)d_in[5];
    const float* bias_res  = (const float*)d_in[6];
    const float* bias_pos  = (const float*)d_in[7];
    float* out             = (float*)d_out;

    mhc_residual_kernel<<<BT, 256>>>(
        (const float4*)x, (const float4*)lo,
        H_res, H_pos, alpha_res, alpha_pos,
        (const float4*)bias_res, (const float4*)bias_pos,
        (float4*)out);
}

// round 7
// speedup vs baseline: 1.2751x; 1.2751x over previous
#include <cuda_runtime.h>
#include <cstdint>

// Problem constants (fixed by the reference: B=4, T=2048, S=4, D=1024)
#define BT      8192        // B*T
#define SDIM    4
#define DDIM    1024
#define DVEC    256         // D/4 float4 per row
#define SINKHORN_ITERS 20
#define EPS_SK  1e-8f

__device__ __forceinline__ float rcp_approx(float x) {
    float r;
    asm("rcp.approx.f32 %0, %1;" : "=f"(r) : "f"(x));
    return r;
}

// ---------------------------------------------------------------------------
// Persistent kernel, single wave (grid = 4 * num_SMs). Each block:
//   1. warp 0 lanes 0..15: shfl-parallel 4x4 Sinkhorn -> sM, sg (~3K cycles,
//      one time, overlapped with the first tile's DRAM loads from other warps'
//      perspective: warps 1..7 fold the 16KB bias into smem meanwhile)
//   2. grid-stride loop over bt tiles: the proven 40.5us R2 body.
//   out[bt,s,dv] = sum_sp M[sp][s]*x[bt,sp,dv] + g[s]*lo[bt,dv] + biasC[s,dv]
// No global flags / fences / atomics -> replay-deterministic by construction.
// ---------------------------------------------------------------------------
__global__ __launch_bounds__(256)
void mhc_residual_kernel(const float4* __restrict__ x,
                         const float4* __restrict__ lo,
                         const float*  __restrict__ H_res,
                         const float*  __restrict__ H_pos,
                         const float*  __restrict__ alpha_res,
                         const float*  __restrict__ alpha_pos,
                         const float4* __restrict__ br,
                         const float4* __restrict__ bp,
                         float4* __restrict__ out)
{
    __shared__ float  sM[16];           // M[sp*4+s] = (sp==s) + a_res*P[sp][s]
    __shared__ float  sg[4];            // alpha_pos * H_pos[s]
    __shared__ float4 sB[SDIM * DVEC];  // bias_res + bias_pos, [s][dvec] (16KB)

    const unsigned tid = threadIdx.x;

    // ---- one-time per-block prep (amortized over ~14 tiles) ----
    if (tid < 32) {
        if (tid < 16) {
            // Warp-parallel Sinkhorn: lane = r*4 + c holds P[r][c]
            const unsigned lane = tid;
            float h = __ldg(H_res + lane);
            float m = fmaxf(h, __shfl_xor_sync(0xffffu, h, 1));
            m = fmaxf(m, __shfl_xor_sync(0xffffu, m, 2));
            float v = __expf(h - m);
            #pragma unroll 1
            for (int it = 0; it < SINKHORN_ITERS; it++) {
                float s = v + __shfl_xor_sync(0xffffu, v, 1);   // row sum (over c)
                s += __shfl_xor_sync(0xffffu, s, 2);
                v *= rcp_approx(s + EPS_SK);
                float t = v + __shfl_xor_sync(0xffffu, v, 4);   // col sum (over r)
                t += __shfl_xor_sync(0xffffu, t, 8);
                v *= rcp_approx(t + EPS_SK);
            }
            float ar = __ldg(alpha_res);
            float diag = ((lane >> 2) == (lane & 3)) ? 1.0f : 0.0f;
            sM[lane] = diag + ar * v;
            if (lane < 4)
                sg[lane] = __ldg(alpha_pos) * __ldg(H_pos + lane);
        }
    } else {
        // Warps 1..7 (224 threads): bias fold into smem, 1024 float4
        for (unsigned j = tid - 32; j < SDIM * DVEC; j += 224) {
            float4 a = __ldg(br + j);
            float4 c = __ldg(bp + j);
            float4 b;
            b.x = a.x + c.x; b.y = a.y + c.y; b.z = a.z + c.z; b.w = a.w + c.w;
            sB[j] = b;
        }
    }
    __syncthreads();

    // Hoist M and g into registers (20 scalars), bias stays in smem.
    float M00 = sM[0],  M01 = sM[1],  M02 = sM[2],  M03 = sM[3];
    float M10 = sM[4],  M11 = sM[5],  M12 = sM[6],  M13 = sM[7];
    float M20 = sM[8],  M21 = sM[9],  M22 = sM[10], M23 = sM[11];
    float M30 = sM[12], M31 = sM[13], M32 = sM[14], M33 = sM[15];
    float g0 = sg[0], g1 = sg[1], g2 = sg[2], g3 = sg[3];

    // ---- grid-stride main loop ----
    for (unsigned bt = blockIdx.x; bt < BT; bt += gridDim.x) {
        const float4* xr = x + (size_t)bt * (SDIM * DVEC) + tid;
        float4 x0 = __ldg(xr + 0 * DVEC);
        float4 x1 = __ldg(xr + 1 * DVEC);
        float4 x2 = __ldg(xr + 2 * DVEC);
        float4 x3 = __ldg(xr + 3 * DVEC);
        float4 l  = __ldg(lo + (size_t)bt * DVEC + tid);

        float4* outr = out + (size_t)bt * (SDIM * DVEC) + tid;

        // s = 0
        {
            float4 b = sB[0 * DVEC + tid];
            float4 o;
            o.x = fmaf(M00, x0.x, fmaf(M10, x1.x, fmaf(M20, x2.x, fmaf(M30, x3.x, fmaf(g0, l.x, b.x)))));
            o.y = fmaf(M00, x0.y, fmaf(M10, x1.y, fmaf(M20, x2.y, fmaf(M30, x3.y, fmaf(g0, l.y, b.y)))));
            o.z = fmaf(M00, x0.z, fmaf(M10, x1.z, fmaf(M20, x2.z, fmaf(M30, x3.z, fmaf(g0, l.z, b.z)))));
            o.w = fmaf(M00, x0.w, fmaf(M10, x1.w, fmaf(M20, x2.w, fmaf(M30, x3.w, fmaf(g0, l.w, b.w)))));
            outr[0 * DVEC] = o;
        }
        // s = 1
        {
            float4 b = sB[1 * DVEC + tid];
            float4 o;
            o.x = fmaf(M01, x0.x, fmaf(M11, x1.x, fmaf(M21, x2.x, fmaf(M31, x3.x, fmaf(g1, l.x, b.x)))));
            o.y = fmaf(M01, x0.y, fmaf(M11, x1.y, fmaf(M21, x2.y, fmaf(M31, x3.y, fmaf(g1, l.y, b.y)))));
            o.z = fmaf(M01, x0.z, fmaf(M11, x1.z, fmaf(M21, x2.z, fmaf(M31, x3.z, fmaf(g1, l.z, b.z)))));
            o.w = fmaf(M01, x0.w, fmaf(M11, x1.w, fmaf(M21, x2.w, fmaf(M31, x3.w, fmaf(g1, l.w, b.w)))));
            outr[1 * DVEC] = o;
        }
        // s = 2
        {
            float4 b = sB[2 * DVEC + tid];
            float4 o;
            o.x = fmaf(M02, x0.x, fmaf(M12, x1.x, fmaf(M22, x2.x, fmaf(M32, x3.x, fmaf(g2, l.x, b.x)))));
            o.y = fmaf(M02, x0.y, fmaf(M12, x1.y, fmaf(M22, x2.y, fmaf(M32, x3.y, fmaf(g2, l.y, b.y)))));
            o.z = fmaf(M02, x0.z, fmaf(M12, x1.z, fmaf(M22, x2.z, fmaf(M32, x3.z, fmaf(g2, l.z, b.z)))));
            o.w = fmaf(M02, x0.w, fmaf(M12, x1.w, fmaf(M22, x2.w, fmaf(M32, x3.w, fmaf(g2, l.w, b.w)))));
            outr[2 * DVEC] = o;
        }
        // s = 3
        {
            float4 b = sB[3 * DVEC + tid];
            float4 o;
            o.x = fmaf(M03, x0.x, fmaf(M13, x1.x, fmaf(M23, x2.x, fmaf(M33, x3.x, fmaf(g3, l.x, b.x)))));
            o.y = fmaf(M03, x0.y, fmaf(M13, x1.y, fmaf(M23, x2.y, fmaf(M33, x3.y, fmaf(g3, l.y, b.y)))));
            o.z = fmaf(M03, x0.z, fmaf(M13, x1.z, fmaf(M23, x2.z, fmaf(M33, x3.z, fmaf(g3, l.z, b.z)))));
            o.w = fmaf(M03, x0.w, fmaf(M13, x1.w, fmaf(M23, x2.w, fmaf(M33, x3.w, fmaf(g3, l.w, b.w)))));
            outr[3 * DVEC] = o;
        }
    }
}

// ---------------------------------------------------------------------------
// Launch. Inputs per metadata order:
//   0: x (B,T,S,D) f32   1: layer_output (B,T,D) f32   2: H_res (S,S) f32
//   3: H_pos (S,1) f32   4: alpha_res f32 scalar        5: alpha_pos f32 scalar
//   6: bias_res (S,D)    7: bias_pos (S,D)
// ---------------------------------------------------------------------------
extern "C" void kernel_launch(void* const* d_in, const int* in_sizes, int n_in,
                              void* d_out, int out_size)
{
    const float* x         = (const float*)d_in[0];
    const float* lo        = (const float*)d_in[1];
    const float* H_res     = (const float*)d_in[2];
    const float* H_pos     = (const float*)d_in[3];
    const float* alpha_res = (const float*)d_in[4];
    const float* alpha_pos = (const float*)d_in[5];
    const float* bias_res  = (const float*)d_in[6];
    const float* bias_pos  = (const float*)d_in[7];
    float* out             = (float*)d_out;

    // One resident wave: 4 blocks per SM (256 thr, <=64 regs, 16.1KB smem).
    int sms = 148;
    cudaDeviceGetAttribute(&sms, cudaDevAttrMultiProcessorCount, 0);
    unsigned grid = (unsigned)(4 * sms);
    if (grid > BT) grid = BT;

    mhc_residual_kernel<<<grid, 256>>>(
        (const float4*)x, (const float4*)lo,
        H_res, H_pos, alpha_res, alpha_pos,
        (const float4*)bias_res, (const float4*)bias_pos,
        (float4*)out);
}

// round 8
// speedup vs baseline: 1.3435x; 1.0536x over previous
#include <cuda_runtime.h>
#include <cstdint>

// Problem constants (fixed by the reference: B=4, T=2048, S=4, D=1024)
#define BT      8192        // B*T
#define SDIM    4
#define DDIM    1024
#define DVEC    256         // D/4 float4 per row
#define SINKHORN_ITERS 20
#define EPS_SK  1e-8f

// Device-side scratch (allocation-free rule: use __device__ globals)
__device__ float d_M[16];               // M[sp*4+s] = (sp==s) + a_res*P[sp][s]
__device__ float d_g[4];                // alpha_pos * H_pos[s]
__device__ float d_biasC[SDIM * DDIM];  // bias_res + bias_pos, [s][d]

__device__ __forceinline__ float rcp_approx(float x) {
    float r;
    asm("rcp.approx.f32 %0, %1;" : "=f"(r) : "f"(x));
    return r;
}

// ---------------------------------------------------------------------------
// Prep (~1us): warp-parallel 4x4 Sinkhorn on lanes 0..15 (shfl reductions,
// rcp.approx) while the whole 256-thread block folds the 16KB bias via float4.
// ---------------------------------------------------------------------------
__global__ __launch_bounds__(256)
void prep_kernel(const float*  __restrict__ H_res,
                 const float*  __restrict__ H_pos,
                 const float*  __restrict__ alpha_res,
                 const float*  __restrict__ alpha_pos,
                 const float4* __restrict__ br,
                 const float4* __restrict__ bp)
{
    const unsigned tid = threadIdx.x;

    // Bias fold: 1024 float4, 4 per thread
    float4* biasC4 = reinterpret_cast<float4*>(d_biasC);
    #pragma unroll
    for (int i = 0; i < 4; i++) {
        unsigned j = tid + i * 256;
        float4 a = __ldg(br + j);
        float4 c = __ldg(bp + j);
        float4 b;
        b.x = a.x + c.x; b.y = a.y + c.y; b.z = a.z + c.z; b.w = a.w + c.w;
        biasC4[j] = b;
    }

    // Warp 0, lanes 0..15: Sinkhorn. lane = r*4 + c holds P[r][c].
    if (tid < 16) {
        const unsigned lane = tid;
        float h = __ldg(H_res + lane);
        float m = fmaxf(h, __shfl_xor_sync(0xffffu, h, 1));
        m = fmaxf(m, __shfl_xor_sync(0xffffu, m, 2));
        float v = __expf(h - m);
        #pragma unroll 1
        for (int it = 0; it < SINKHORN_ITERS; it++) {
            float s = v + __shfl_xor_sync(0xffffu, v, 1);   // row sum (over c)
            s += __shfl_xor_sync(0xffffu, s, 2);
            v *= rcp_approx(s + EPS_SK);
            float t = v + __shfl_xor_sync(0xffffu, v, 4);   // col sum (over r)
            t += __shfl_xor_sync(0xffffu, t, 8);
            v *= rcp_approx(t + EPS_SK);
        }
        float ar = __ldg(alpha_res);
        float diag = ((lane >> 2) == (lane & 3)) ? 1.0f : 0.0f;
        d_M[lane] = diag + ar * v;
        if (lane < 4)
            d_g[lane] = __ldg(alpha_pos) * __ldg(H_pos + lane);
    }
}

// ---------------------------------------------------------------------------
// Main kernel — the proven 40.5us configuration (R2): one block per bt tile,
// grid 8192, front-batched __ldg loads, precombined bias via __ldg, 64 regs.
//   out[bt,s,dv] = sum_sp M[sp][s]*x[bt,sp,dv] + g[s]*lo[bt,dv] + biasC[s,dv]
// ---------------------------------------------------------------------------
__global__ __launch_bounds__(256)
void mhc_residual_kernel(const float4* __restrict__ x,
                         const float4* __restrict__ lo,
                         float4* __restrict__ out)
{
    __shared__ float sM[16];
    __shared__ float sg[4];
    if (threadIdx.x < 16) sM[threadIdx.x] = d_M[threadIdx.x];
    if (threadIdx.x < 4)  sg[threadIdx.x] = d_g[threadIdx.x];
    __syncthreads();

    unsigned idx = blockIdx.x * blockDim.x + threadIdx.x;  // 0 .. BT*DVEC-1
    unsigned dvec = idx & (DVEC - 1);
    unsigned bt   = idx >> 8;  // log2(DVEC) = 8

    const float4* xr = x + (size_t)bt * (SDIM * DVEC) + dvec;
    float4 x0 = __ldg(xr + 0 * DVEC);
    float4 x1 = __ldg(xr + 1 * DVEC);
    float4 x2 = __ldg(xr + 2 * DVEC);
    float4 x3 = __ldg(xr + 3 * DVEC);
    float4 l  = __ldg(lo + (size_t)bt * DVEC + dvec);

    const float4* bC = reinterpret_cast<const float4*>(d_biasC) + dvec;
    float4* outr = out + (size_t)bt * (SDIM * DVEC) + dvec;

#pragma unroll
    for (int s = 0; s < 4; s++) {
        float m0 = sM[0 * 4 + s];
        float m1 = sM[1 * 4 + s];
        float m2 = sM[2 * 4 + s];
        float m3 = sM[3 * 4 + s];
        float g  = sg[s];
        float4 b = __ldg(bC + s * DVEC);
        float4 o;
        o.x = fmaf(m0, x0.x, fmaf(m1, x1.x, fmaf(m2, x2.x, fmaf(m3, x3.x, fmaf(g, l.x, b.x)))));
        o.y = fmaf(m0, x0.y, fmaf(m1, x1.y, fmaf(m2, x2.y, fmaf(m3, x3.y, fmaf(g, l.y, b.y)))));
        o.z = fmaf(m0, x0.z, fmaf(m1, x1.z, fmaf(m2, x2.z, fmaf(m3, x3.z, fmaf(g, l.z, b.z)))));
        o.w = fmaf(m0, x0.w, fmaf(m1, x1.w, fmaf(m2, x2.w, fmaf(m3, x3.w, fmaf(g, l.w, b.w)))));
        outr[s * DVEC] = o;
    }
}

// ---------------------------------------------------------------------------
// Launch. Inputs per metadata order:
//   0: x (B,T,S,D) f32   1: layer_output (B,T,D) f32   2: H_res (S,S) f32
//   3: H_pos (S,1) f32   4: alpha_res f32 scalar        5: alpha_pos f32 scalar
//   6: bias_res (S,D)    7: bias_pos (S,D)
// ---------------------------------------------------------------------------
extern "C" void kernel_launch(void* const* d_in, const int* in_sizes, int n_in,
                              void* d_out, int out_size)
{
    const float* x         = (const float*)d_in[0];
    const float* lo        = (const float*)d_in[1];
    const float* H_res     = (const float*)d_in[2];
    const float* H_pos     = (const float*)d_in[3];
    const float* alpha_res = (const float*)d_in[4];
    const float* alpha_pos = (const float*)d_in[5];
    const float* bias_res  = (const float*)d_in[6];
    const float* bias_pos  = (const float*)d_in[7];
    float* out             = (float*)d_out;

    prep_kernel<<<1, 256>>>(H_res, H_pos, alpha_res, alpha_pos,
                            (const float4*)bias_res, (const float4*)bias_pos);

    const unsigned total = BT * DVEC;          // 2,097,152 threads
    const unsigned threads = 256;
    mhc_residual_kernel<<<total / threads, threads>>>(
        (const float4*)x, (const float4*)lo, (float4*)out);
}

// round 9
// speedup vs baseline: 1.3443x; 1.0006x over previous
#include <cuda_runtime.h>
#include <cstdint>

// Problem constants (fixed by the reference: B=4, T=2048, S=4, D=1024)
#define BT      8192        // B*T
#define SDIM    4
#define DDIM    1024
#define DVEC    256         // D/4 float4 per row
#define SINKHORN_ITERS 20
#define EPS_SK  1e-8f

// Device-side scratch (allocation-free rule: use __device__ globals)
__device__ float d_M[16];               // M[sp*4+s] = (sp==s) + a_res*P[sp][s]
__device__ float d_g[4];                // alpha_pos * H_pos[s]
__device__ float d_biasC[SDIM * DDIM];  // bias_res + bias_pos, [s][d]

__device__ __forceinline__ float rcp_approx(float x) {
    float r;
    asm("rcp.approx.f32 %0, %1;" : "=f"(r) : "f"(x));
    return r;
}

// ---------------------------------------------------------------------------
// Prep (~1us): warp-parallel 4x4 Sinkhorn on lanes 0..15 (shfl reductions,
// rcp.approx) while the whole 256-thread block folds the 16KB bias via float4.
// ---------------------------------------------------------------------------
__global__ __launch_bounds__(256)
void prep_kernel(const float*  __restrict__ H_res,
                 const float*  __restrict__ H_pos,
                 const float*  __restrict__ alpha_res,
                 const float*  __restrict__ alpha_pos,
                 const float4* __restrict__ br,
                 const float4* __restrict__ bp)
{
    const unsigned tid = threadIdx.x;

    // Bias fold: 1024 float4, 4 per thread
    float4* biasC4 = reinterpret_cast<float4*>(d_biasC);
    #pragma unroll
    for (int i = 0; i < 4; i++) {
        unsigned j = tid + i * 256;
        float4 a = __ldg(br + j);
        float4 c = __ldg(bp + j);
        float4 b;
        b.x = a.x + c.x; b.y = a.y + c.y; b.z = a.z + c.z; b.w = a.w + c.w;
        biasC4[j] = b;
    }

    // Warp 0, lanes 0..15: Sinkhorn. lane = r*4 + c holds P[r][c].
    if (tid < 16) {
        const unsigned lane = tid;
        float h = __ldg(H_res + lane);
        float m = fmaxf(h, __shfl_xor_sync(0xffffu, h, 1));
        m = fmaxf(m, __shfl_xor_sync(0xffffu, m, 2));
        float v = __expf(h - m);
        #pragma unroll 1
        for (int it = 0; it < SINKHORN_ITERS; it++) {
            float s = v + __shfl_xor_sync(0xffffu, v, 1);   // row sum (over c)
            s += __shfl_xor_sync(0xffffu, s, 2);
            v *= rcp_approx(s + EPS_SK);
            float t = v + __shfl_xor_sync(0xffffu, v, 4);   // col sum (over r)
            t += __shfl_xor_sync(0xffffu, t, 8);
            v *= rcp_approx(t + EPS_SK);
        }
        float ar = __ldg(alpha_res);
        float diag = ((lane >> 2) == (lane & 3)) ? 1.0f : 0.0f;
        d_M[lane] = diag + ar * v;
        if (lane < 4)
            d_g[lane] = __ldg(alpha_pos) * __ldg(H_pos + lane);
    }
}

// ---------------------------------------------------------------------------
// Main kernel, ILP=2: each thread handles TWO consecutive bt tiles.
// 10 front-batched LDG.128 per thread (vs 5) -> more outstanding DRAM loads
// per SM even at 3 CTAs/SM; bias float4 loaded once per s, reused for both
// tiles (halves bias L2 traffic).
//   out[bt,s,dv] = sum_sp M[sp][s]*x[bt,sp,dv] + g[s]*lo[bt,dv] + biasC[s,dv]
// ---------------------------------------------------------------------------
__global__ __launch_bounds__(256, 3)
void mhc_residual_kernel(const float4* __restrict__ x,
                         const float4* __restrict__ lo,
                         float4* __restrict__ out)
{
    __shared__ float sM[16];
    __shared__ float sg[4];
    if (threadIdx.x < 16) sM[threadIdx.x] = d_M[threadIdx.x];
    if (threadIdx.x < 4)  sg[threadIdx.x] = d_g[threadIdx.x];
    __syncthreads();

    const unsigned dvec = threadIdx.x;            // 0..255
    const unsigned bt0  = blockIdx.x * 2u;        // tiles bt0, bt0+1

    // Front-batch all DRAM loads for both tiles (rows are contiguous:
    // tile B starts SDIM*DVEC float4 after tile A).
    const float4* xr = x + (size_t)bt0 * (SDIM * DVEC) + dvec;
    float4 xA0 = __ldg(xr + 0 * DVEC);
    float4 xA1 = __ldg(xr + 1 * DVEC);
    float4 xA2 = __ldg(xr + 2 * DVEC);
    float4 xA3 = __ldg(xr + 3 * DVEC);
    float4 xB0 = __ldg(xr + 4 * DVEC);
    float4 xB1 = __ldg(xr + 5 * DVEC);
    float4 xB2 = __ldg(xr + 6 * DVEC);
    float4 xB3 = __ldg(xr + 7 * DVEC);
    const float4* lr = lo + (size_t)bt0 * DVEC + dvec;
    float4 lA = __ldg(lr + 0 * DVEC);
    float4 lB = __ldg(lr + 1 * DVEC);

    const float4* bC = reinterpret_cast<const float4*>(d_biasC) + dvec;
    float4* outr = out + (size_t)bt0 * (SDIM * DVEC) + dvec;

#pragma unroll
    for (int s = 0; s < 4; s++) {
        float m0 = sM[0 * 4 + s];
        float m1 = sM[1 * 4 + s];
        float m2 = sM[2 * 4 + s];
        float m3 = sM[3 * 4 + s];
        float g  = sg[s];
        float4 b = __ldg(bC + s * DVEC);   // loaded once, used for both tiles
        float4 o;
        // tile A
        o.x = fmaf(m0, xA0.x, fmaf(m1, xA1.x, fmaf(m2, xA2.x, fmaf(m3, xA3.x, fmaf(g, lA.x, b.x)))));
        o.y = fmaf(m0, xA0.y, fmaf(m1, xA1.y, fmaf(m2, xA2.y, fmaf(m3, xA3.y, fmaf(g, lA.y, b.y)))));
        o.z = fmaf(m0, xA0.z, fmaf(m1, xA1.z, fmaf(m2, xA2.z, fmaf(m3, xA3.z, fmaf(g, lA.z, b.z)))));
        o.w = fmaf(m0, xA0.w, fmaf(m1, xA1.w, fmaf(m2, xA2.w, fmaf(m3, xA3.w, fmaf(g, lA.w, b.w)))));
        outr[s * DVEC] = o;
        // tile B
        o.x = fmaf(m0, xB0.x, fmaf(m1, xB1.x, fmaf(m2, xB2.x, fmaf(m3, xB3.x, fmaf(g, lB.x, b.x)))));
        o.y = fmaf(m0, xB0.y, fmaf(m1, xB1.y, fmaf(m2, xB2.y, fmaf(m3, xB3.y, fmaf(g, lB.y, b.y)))));
        o.z = fmaf(m0, xB0.z, fmaf(m1, xB1.z, fmaf(m2, xB2.z, fmaf(m3, xB3.z, fmaf(g, lB.z, b.z)))));
        o.w = fmaf(m0, xB0.w, fmaf(m1, xB1.w, fmaf(m2, xB2.w, fmaf(m3, xB3.w, fmaf(g, lB.w, b.w)))));
        outr[(SDIM + s) * DVEC] = o;
    }
}

// ---------------------------------------------------------------------------
// Launch. Inputs per metadata order:
//   0: x (B,T,S,D) f32   1: layer_output (B,T,D) f32   2: H_res (S,S) f32
//   3: H_pos (S,1) f32   4: alpha_res f32 scalar        5: alpha_pos f32 scalar
//   6: bias_res (S,D)    7: bias_pos (S,D)
// ---------------------------------------------------------------------------
extern "C" void kernel_launch(void* const* d_in, const int* in_sizes, int n_in,
                              void* d_out, int out_size)
{
    const float* x         = (const float*)d_in[0];
    const float* lo        = (const float*)d_in[1];
    const float* H_res     = (const float*)d_in[2];
    const float* H_pos     = (const float*)d_in[3];
    const float* alpha_res = (const float*)d_in[4];
    const float* alpha_pos = (const float*)d_in[5];
    const float* bias_res  = (const float*)d_in[6];
    const float* bias_pos  = (const float*)d_in[7];
    float* out             = (float*)d_out;

    prep_kernel<<<1, 256>>>(H_res, H_pos, alpha_res, alpha_pos,
                            (const float4*)bias_res, (const float4*)bias_pos);

    mhc_residual_kernel<<<BT / 2, 256>>>(
        (const float4*)x, (const float4*)lo, (float4*)out);
}

// round 10
// speedup vs baseline: 1.3754x; 1.0232x over previous
#include <cuda_runtime.h>
#include <cstdint>

// Problem constants (fixed by the reference: B=4, T=2048, S=4, D=1024)
#define BT      8192        // B*T
#define SDIM    4
#define DDIM    1024
#define DVEC    256         // D/4 float4 per row
#define SINKHORN_ITERS 20
#define EPS_SK  1e-8f

// Device-side scratch (allocation-free rule: use __device__ globals)
__device__ float d_M[16];               // M[sp*4+s] = (sp==s) + a_res*P[sp][s]
__device__ float d_g[4];                // alpha_pos * H_pos[s]
__device__ float d_biasC[SDIM * DDIM];  // bias_res + bias_pos, [s][d]

__device__ __forceinline__ float rcp_approx(float x) {
    float r;
    asm("rcp.approx.f32 %0, %1;" : "=f"(r) : "f"(x));
    return r;
}

// ---------------------------------------------------------------------------
// Prep (~1us): warp-parallel 4x4 Sinkhorn on lanes 0..15 (shfl reductions,
// rcp.approx) while the whole 256-thread block folds the 16KB bias via float4.
// ---------------------------------------------------------------------------
__global__ __launch_bounds__(256)
void prep_kernel(const float*  __restrict__ H_res,
                 const float*  __restrict__ H_pos,
                 const float*  __restrict__ alpha_res,
                 const float*  __restrict__ alpha_pos,
                 const float4* __restrict__ br,
                 const float4* __restrict__ bp)
{
    const unsigned tid = threadIdx.x;

    // Bias fold: 1024 float4, 4 per thread
    float4* biasC4 = reinterpret_cast<float4*>(d_biasC);
    #pragma unroll
    for (int i = 0; i < 4; i++) {
        unsigned j = tid + i * 256;
        float4 a = __ldg(br + j);
        float4 c = __ldg(bp + j);
        float4 b;
        b.x = a.x + c.x; b.y = a.y + c.y; b.z = a.z + c.z; b.w = a.w + c.w;
        biasC4[j] = b;
    }

    // Warp 0, lanes 0..15: Sinkhorn. lane = r*4 + c holds P[r][c].
    if (tid < 16) {
        const unsigned lane = tid;
        float h = __ldg(H_res + lane);
        float m = fmaxf(h, __shfl_xor_sync(0xffffu, h, 1));
        m = fmaxf(m, __shfl_xor_sync(0xffffu, m, 2));
        float v = __expf(h - m);
        #pragma unroll 1
        for (int it = 0; it < SINKHORN_ITERS; it++) {
            float s = v + __shfl_xor_sync(0xffffu, v, 1);   // row sum (over c)
            s += __shfl_xor_sync(0xffffu, s, 2);
            v *= rcp_approx(s + EPS_SK);
            float t = v + __shfl_xor_sync(0xffffu, v, 4);   // col sum (over r)
            t += __shfl_xor_sync(0xffffu, t, 8);
            v *= rcp_approx(t + EPS_SK);
        }
        float ar = __ldg(alpha_res);
        float diag = ((lane >> 2) == (lane & 3)) ? 1.0f : 0.0f;
        d_M[lane] = diag + ar * v;
        if (lane < 4)
            d_g[lane] = __ldg(alpha_pos) * __ldg(H_pos + lane);
    }
}

// ---------------------------------------------------------------------------
// Main kernel — proven R8 structure (grid 8192, 5 front-batched LDG.128,
// precombined bias, 64-reg envelope) + streaming cache hints as the single
// variable under test: __ldcs on the zero-reuse x/lo streams, __stcs on the
// never-re-read output stream. Bias stays __ldg (hot, L2-resident).
//   out[bt,s,dv] = sum_sp M[sp][s]*x[bt,sp,dv] + g[s]*lo[bt,dv] + biasC[s,dv]
// ---------------------------------------------------------------------------
__global__ __launch_bounds__(256, 4)
void mhc_residual_kernel(const float4* __restrict__ x,
                         const float4* __restrict__ lo,
                         float4* __restrict__ out)
{
    __shared__ float sM[16];
    __shared__ float sg[4];
    if (threadIdx.x < 16) sM[threadIdx.x] = d_M[threadIdx.x];
    if (threadIdx.x < 4)  sg[threadIdx.x] = d_g[threadIdx.x];
    __syncthreads();

    unsigned idx = blockIdx.x * blockDim.x + threadIdx.x;  // 0 .. BT*DVEC-1
    unsigned dvec = idx & (DVEC - 1);
    unsigned bt   = idx >> 8;  // log2(DVEC) = 8

    const float4* xr = x + (size_t)bt * (SDIM * DVEC) + dvec;
    float4 x0 = __ldcs(xr + 0 * DVEC);
    float4 x1 = __ldcs(xr + 1 * DVEC);
    float4 x2 = __ldcs(xr + 2 * DVEC);
    float4 x3 = __ldcs(xr + 3 * DVEC);
    float4 l  = __ldcs(lo + (size_t)bt * DVEC + dvec);

    const float4* bC = reinterpret_cast<const float4*>(d_biasC) + dvec;
    float4* outr = out + (size_t)bt * (SDIM * DVEC) + dvec;

#pragma unroll
    for (int s = 0; s < 4; s++) {
        float m0 = sM[0 * 4 + s];
        float m1 = sM[1 * 4 + s];
        float m2 = sM[2 * 4 + s];
        float m3 = sM[3 * 4 + s];
        float g  = sg[s];
        float4 b = __ldg(bC + s * DVEC);
        float4 o;
        o.x = fmaf(m0, x0.x, fmaf(m1, x1.x, fmaf(m2, x2.x, fmaf(m3, x3.x, fmaf(g, l.x, b.x)))));
        o.y = fmaf(m0, x0.y, fmaf(m1, x1.y, fmaf(m2, x2.y, fmaf(m3, x3.y, fmaf(g, l.y, b.y)))));
        o.z = fmaf(m0, x0.z, fmaf(m1, x1.z, fmaf(m2, x2.z, fmaf(m3, x3.z, fmaf(g, l.z, b.z)))));
        o.w = fmaf(m0, x0.w, fmaf(m1, x1.w, fmaf(m2, x2.w, fmaf(m3, x3.w, fmaf(g, l.w, b.w)))));
        __stcs(outr + s * DVEC, o);
    }
}

// ---------------------------------------------------------------------------
// Launch. Inputs per metadata order:
//   0: x (B,T,S,D) f32   1: layer_output (B,T,D) f32   2: H_res (S,S) f32
//   3: H_pos (S,1) f32   4: alpha_res f32 scalar        5: alpha_pos f32 scalar
//   6: bias_res (S,D)    7: bias_pos (S,D)
// ---------------------------------------------------------------------------
extern "C" void kernel_launch(void* const* d_in, const int* in_sizes, int n_in,
                              void* d_out, int out_size)
{
    const float* x         = (const float*)d_in[0];
    const float* lo        = (const float*)d_in[1];
    const float* H_res     = (const float*)d_in[2];
    const float* H_pos     = (const float*)d_in[3];
    const float* alpha_res = (const float*)d_in[4];
    const float* alpha_pos = (const float*)d_in[5];
    const float* bias_res  = (const float*)d_in[6];
    const float* bias_pos  = (const float*)d_in[7];
    float* out             = (float*)d_out;

    prep_kernel<<<1, 256>>>(H_res, H_pos, alpha_res, alpha_pos,
                            (const float4*)bias_res, (const float4*)bias_pos);

    const unsigned total = BT * DVEC;          // 2,097,152 threads
    const unsigned threads = 256;
    mhc_residual_kernel<<<total / threads, threads>>>(
        (const float4*)x, (const float4*)lo, (float4*)out);
}